// round 10
// baseline (speedup 1.0000x reference)
#include <cuda_runtime.h>

// QConv1d, conjugation closed form; the f32x2 lanes hold a CI-PAIR (ci, ci+8).
// No broadcast movs; invariants amortize over 2 ci; NCO=2 co per thread.
// x: (B, CIN, T, 4)   a,b,c: (COUT, CIN, FL)   out: (B, COUT, TOUT, 4)

#define B_    2
#define CIN_  16
#define COUT_ 16
#define T_    2048
#define FL_   9
#define TOUT_ 2040
#define NCO   2        // co per thread
#define GRP   8        // ci-pair groups per block

typedef unsigned long long ull;

__device__ __forceinline__ ull pk2(float lo, float hi) {
    ull r; asm("mov.b64 %0,{%1,%2};" : "=l"(r)
               : "r"(__float_as_uint(lo)), "r"(__float_as_uint(hi)));
    return r;
}
__device__ __forceinline__ void upk2(ull v, float& lo, float& hi) {
    unsigned a, b; asm("mov.b64 {%0,%1},%2;" : "=r"(a), "=r"(b) : "l"(v));
    lo = __uint_as_float(a); hi = __uint_as_float(b);
}
__device__ __forceinline__ ull f2(ull a, ull b, ull c) {
    ull r; asm("fma.rn.f32x2 %0,%1,%2,%3;" : "=l"(r) : "l"(a), "l"(b), "l"(c));
    return r;
}
__device__ __forceinline__ ull m2(ull a, ull b) {
    ull r; asm("mul.rn.f32x2 %0,%1,%2;" : "=l"(r) : "l"(a), "l"(b));
    return r;
}
__device__ __forceinline__ ull a2_(ull a, ull b) {
    ull r; asm("add.rn.f32x2 %0,%1,%2;" : "=l"(r) : "l"(a), "l"(b));
    return r;
}
__device__ __forceinline__ float rcpf(float x) {
    float r; asm("rcp.approx.f32 %0,%1;" : "=f"(r) : "f"(x));
    return r;
}
__device__ __forceinline__ ull rcp2(ull v) {
    float lo, hi; upk2(v, lo, hi);
    return pk2(rcpf(lo), rcpf(hi));
}

__global__ __launch_bounds__(32 * GRP)
void qconv1d_kernel(const float* __restrict__ x,
                    const float* __restrict__ pa,
                    const float* __restrict__ pb,
                    const float* __restrict__ pc,
                    float* __restrict__ out)
{
    __shared__ ull sp[GRP][FL_][3][NCO];     // {a,b,c} packed over (ci, ci+8)
    __shared__ ull red[GRP - 1][32][NCO][4];

    const int tx  = threadIdx.x;
    const int g   = threadIdx.y;             // ci-pair group: lanes (g, g+8)
    const int tid = g * 32 + tx;
    const int t   = blockIdx.x * 32 + tx;
    const int co0 = blockIdx.y * NCO;
    const int b   = blockIdx.z;
    const int tL  = t < TOUT_ ? t : (TOUT_ - 1);

    // pack params: 8*9*3*2 = 432 packed entries, 256 threads
    for (int e = tid; e < GRP * FL_ * 3 * NCO; e += 32 * GRP) {
        const int j   = e % NCO;
        const int rem = e / NCO;
        const int prm = rem % 3;
        const int f   = (rem / 3) % FL_;
        const int gg  = rem / (3 * FL_);
        const int s0 = ((co0 + j) * CIN_ + gg) * FL_ + f;
        const int s1 = s0 + GRP * FL_;       // ci = gg + 8
        const float* P = (prm == 0) ? pa : (prm == 1) ? pb : pc;
        sp[gg][f][prm][j] = pk2(__ldg(P + s0), __ldg(P + s1));
    }
    __syncthreads();

    const float4* xr0 = reinterpret_cast<const float4*>(x)
                      + ((size_t)b * CIN_ + g) * T_ + tL;
    const float4* xr1 = xr0 + (size_t)GRP * T_;      // ci = g + 8

    // center taps for both ci, packed
    const float4 va = __ldg(xr0 + 4);
    const float4 vb = __ldg(xr1 + 4);
    const ull NEG1 = pk2(-1.0f, -1.0f);
    const ull pw2 = pk2(va.x, vb.x);
    const ull vx2 = pk2(va.y, vb.y);
    const ull vy2 = pk2(va.z, vb.z);
    const ull vz2 = pk2(va.w, vb.w);
    const ull vsq2  = f2(vx2, vx2, f2(vy2, vy2, m2(vz2, vz2)));
    const ull nvsq2 = m2(vsq2, NEG1);

    ull aw[NCO], ax[NCO], ay[NCO], az[NCO];
    #pragma unroll
    for (int j = 0; j < NCO; ++j) { aw[j]=0; ax[j]=0; ay[j]=0; az[j]=0; }

    #pragma unroll
    for (int f = 0; f < FL_; ++f) {
        const float4 ua = __ldg(xr0 + f);
        const float4 ub = __ldg(xr1 + f);
        const ull s2  = pk2(ua.x, ub.x);
        const ull ux2 = pk2(ua.y, ub.y);
        const ull uy2 = pk2(ua.z, ub.z);
        const ull uz2 = pk2(ua.w, ub.w);
        const ull nux2 = m2(ux2, NEG1);
        const ull nuy2 = m2(uy2, NEG1);
        const ull nuz2 = m2(uz2, NEG1);

        // packed invariants (serve both ci, all co):
        // R(w) = w^2 u + w (2 v x u) + (2d v - vsq u)
        ull d2 = f2(vx2, ux2, f2(vy2, uy2, m2(vz2, uz2)));
        d2 = a2_(d2, d2);
        ull crx = f2(vy2, uz2, m2(vz2, nuy2)); crx = a2_(crx, crx);
        ull cry = f2(vz2, ux2, m2(vx2, nuz2)); cry = a2_(cry, cry);
        ull crz = f2(vx2, uy2, m2(vy2, nux2)); crz = a2_(crz, crz);
        const ull a0x = f2(d2, vx2, m2(nvsq2, ux2));
        const ull a0y = f2(d2, vy2, m2(nvsq2, uy2));
        const ull a0z = f2(d2, vz2, m2(nvsq2, uz2));

        #pragma unroll
        for (int j = 0; j < NCO; ++j) {
            const ull A2 = sp[g][f][0][j];
            const ull B2 = sp[g][f][1][j];
            const ull C2 = sp[g][f][2][j];

            const ull w2   = a2_(pw2, C2);
            const ull nsq2 = f2(w2, w2, vsq2);
            const ull rn2  = rcp2(nsq2);
            const ull arn2 = m2(A2, rn2);

            const ull Rx = m2(f2(w2, f2(w2, ux2, crx), a0x), arn2);
            const ull Ry = m2(f2(w2, f2(w2, uy2, cry), a0y), arn2);
            const ull Rz = m2(f2(w2, f2(w2, uz2, crz), a0z), arn2);
            const ull Rw = m2(s2, A2);
            const ull qw2 = a2_(s2, B2);

            // acc += (q + b e) (x) R
            aw[j] = f2(qw2, Rw, aw[j]);
            aw[j] = f2(nux2, Rx, aw[j]);
            aw[j] = f2(nuy2, Ry, aw[j]);
            aw[j] = f2(nuz2, Rz, aw[j]);
            ax[j] = f2(qw2, Rx, ax[j]);
            ax[j] = f2(ux2, Rw, ax[j]);
            ax[j] = f2(uy2, Rz, ax[j]);
            ax[j] = f2(nuz2, Ry, ax[j]);
            ay[j] = f2(qw2, Ry, ay[j]);
            ay[j] = f2(nux2, Rz, ay[j]);
            ay[j] = f2(uy2, Rw, ay[j]);
            ay[j] = f2(uz2, Rx, ay[j]);
            az[j] = f2(qw2, Rz, az[j]);
            az[j] = f2(ux2, Ry, az[j]);
            az[j] = f2(nuy2, Rx, az[j]);
            az[j] = f2(uz2, Rw, az[j]);
        }
    }

    // reduce over the 8 ci-pair groups (packed adds), then fold the two halves
    if (g > 0) {
        #pragma unroll
        for (int j = 0; j < NCO; ++j) {
            red[g - 1][tx][j][0] = aw[j];
            red[g - 1][tx][j][1] = ax[j];
            red[g - 1][tx][j][2] = ay[j];
            red[g - 1][tx][j][3] = az[j];
        }
    }
    __syncthreads();
    if (g == 0 && t < TOUT_) {
        #pragma unroll
        for (int j = 0; j < NCO; ++j) {
            ull w = aw[j], X = ax[j], Y = ay[j], Z = az[j];
            #pragma unroll
            for (int k = 0; k < GRP - 1; ++k) {
                w = a2_(w, red[k][tx][j][0]);
                X = a2_(X, red[k][tx][j][1]);
                Y = a2_(Y, red[k][tx][j][2]);
                Z = a2_(Z, red[k][tx][j][3]);
            }
            float w0, w1, x0, x1, y0, y1, z0, z1;
            upk2(w, w0, w1); upk2(X, x0, x1); upk2(Y, y0, y1); upk2(Z, z0, z1);
            reinterpret_cast<float4*>(out)[((size_t)b * COUT_ + co0 + j) * TOUT_ + t]
                = make_float4(w0 + w1, x0 + x1, y0 + y1, z0 + z1);
        }
    }
}

extern "C" void kernel_launch(void* const* d_in, const int* in_sizes, int n_in,
                              void* d_out, int out_size)
{
    const float* x  = (const float*)d_in[0];
    const float* pa = (const float*)d_in[1];
    const float* pb = (const float*)d_in[2];
    const float* pc = (const float*)d_in[3];
    float* out = (float*)d_out;

    dim3 block(32, GRP, 1);
    dim3 grid((TOUT_ + 31) / 32, COUT_ / NCO, B_);
    qconv1d_kernel<<<grid, block>>>(x, pa, pb, pc, out);
}

// round 11
// speedup vs baseline: 1.3924x; 1.3924x over previous
#include <cuda_runtime.h>

// QConv1d, conjugation closed form; f32x2 lanes hold the CO-PAIR (R7 shape).
// Refinement: pre-doubled v broadcasts remove the 4 doubling adds per tap.
// x: (B, CIN, T, 4)   a,b,c: (COUT, CIN, FL)   out: (B, COUT, TOUT, 4)

#define B_    2
#define CIN_  16
#define COUT_ 16
#define T_    2048
#define FL_   9
#define TOUT_ 2040
#define NQ    2        // co per thread (packed in f32x2 halves)

typedef unsigned long long ull;

__device__ __forceinline__ ull pk2(float lo, float hi) {
    ull r; asm("mov.b64 %0,{%1,%2};" : "=l"(r)
               : "r"(__float_as_uint(lo)), "r"(__float_as_uint(hi)));
    return r;
}
__device__ __forceinline__ void upk2(ull v, float& lo, float& hi) {
    unsigned a, b; asm("mov.b64 {%0,%1},%2;" : "=r"(a), "=r"(b) : "l"(v));
    lo = __uint_as_float(a); hi = __uint_as_float(b);
}
__device__ __forceinline__ ull bc2(float v) { return pk2(v, v); }
__device__ __forceinline__ ull f2(ull a, ull b, ull c) {
    ull r; asm("fma.rn.f32x2 %0,%1,%2,%3;" : "=l"(r) : "l"(a), "l"(b), "l"(c));
    return r;
}
__device__ __forceinline__ ull m2(ull a, ull b) {
    ull r; asm("mul.rn.f32x2 %0,%1,%2;" : "=l"(r) : "l"(a), "l"(b));
    return r;
}
__device__ __forceinline__ ull a2_(ull a, ull b) {
    ull r; asm("add.rn.f32x2 %0,%1,%2;" : "=l"(r) : "l"(a), "l"(b));
    return r;
}
__device__ __forceinline__ float rcpf(float x) {
    float r; asm("rcp.approx.f32 %0,%1;" : "=f"(r) : "f"(x));
    return r;
}

__global__ __launch_bounds__(32 * CIN_)
void qconv1d_kernel(const float* __restrict__ x,
                    const float* __restrict__ pa,
                    const float* __restrict__ pb,
                    const float* __restrict__ pc,
                    float* __restrict__ out)
{
    __shared__ ull sp[CIN_][FL_][3];            // packed {a,b,c} over the co-pair
    __shared__ ull red[CIN_ - 1][32][4];        // packed accumulators

    const int tx  = threadIdx.x;
    const int ci  = threadIdx.y;
    const int tid = ci * 32 + tx;
    const int t   = blockIdx.x * 32 + tx;
    const int co0 = blockIdx.y * NQ;
    const int b   = blockIdx.z;
    const int tL  = t < TOUT_ ? t : (TOUT_ - 1);  // clamp loads, predicate store

    // pack params over the co-pair: 144 entries, 512 threads
    if (tid < CIN_ * FL_) {
        const int cci = tid / FL_, f = tid % FL_;
        const int s0 = (co0 * CIN_ + cci) * FL_ + f;
        const int s1 = s0 + CIN_ * FL_;
        sp[cci][f][0] = pk2(__ldg(pa + s0), __ldg(pa + s1));
        sp[cci][f][1] = pk2(__ldg(pb + s0), __ldg(pb + s1));
        sp[cci][f][2] = pk2(__ldg(pc + s0), __ldg(pc + s1));
    }
    __syncthreads();

    const float4* xr = reinterpret_cast<const float4*>(x)
                     + ((size_t)b * CIN_ + ci) * T_ + tL;

    // center tap qp — scalar; one-time doubled copies remove doubling adds in-loop
    const float4 v4 = __ldg(xr + 4);
    const float pw = v4.x, vx = v4.y, vy = v4.z, vz = v4.w;
    const float vdx = vx + vx, vdy = vy + vy, vdz = vz + vz;   // 2v
    const float vsq  = vx * vx + vy * vy + vz * vz;
    const float nvsq = -vsq;
    const ull pw2  = bc2(pw);
    const ull vsq2 = bc2(vsq);
    const ull NEG1 = bc2(-1.0f);

    ull aw = 0, ax = 0, ay = 0, az = 0;

    #pragma unroll
    for (int f = 0; f < FL_; ++f) {
        const float4 u4 = __ldg(xr + f);
        const float s = u4.x, ux = u4.y, uy = u4.z, uz = u4.w;

        // scalar co-invariants (pre-doubled): R(w) = w^2 u + w*cr + (dd v - vsq u)
        const float dd  = vdx*ux + vdy*uy + vdz*uz;            // 2 v.u
        const float crx = vdy*uz - vdz*uy;                     // 2 (v x u)
        const float cry = vdz*ux - vdx*uz;
        const float crz = vdx*uy - vdy*ux;
        const float a0x = fmaf(dd, vx, nvsq * ux);
        const float a0y = fmaf(dd, vy, nvsq * uy);
        const float a0z = fmaf(dd, vz, nvsq * uz);

        // broadcast to packed lanes (once per f, shared by both co)
        const ull s2   = bc2(s);
        const ull ux2  = bc2(ux);
        const ull uy2  = bc2(uy);
        const ull uz2  = bc2(uz);
        const ull crx2 = bc2(crx);
        const ull cry2 = bc2(cry);
        const ull crz2 = bc2(crz);
        const ull a0x2 = bc2(a0x);
        const ull a0y2 = bc2(a0y);
        const ull a0z2 = bc2(a0z);

        // packed per-co body (both co at once)
        const ull A2 = sp[ci][f][0];
        const ull B2 = sp[ci][f][1];
        const ull C2 = sp[ci][f][2];

        const ull w2   = a2_(pw2, C2);
        const ull nsq2 = f2(w2, w2, vsq2);
        float nlo, nhi; upk2(nsq2, nlo, nhi);
        const ull rn2  = pk2(rcpf(nlo), rcpf(nhi));
        const ull arn2 = m2(A2, rn2);

        const ull Rx = m2(f2(w2, f2(w2, ux2, crx2), a0x2), arn2);
        const ull Ry = m2(f2(w2, f2(w2, uy2, cry2), a0y2), arn2);
        const ull Rz = m2(f2(w2, f2(w2, uz2, crz2), a0z2), arn2);
        const ull Rw = m2(s2, A2);
        const ull nRx = m2(Rx, NEG1);
        const ull nRy = m2(Ry, NEG1);
        const ull nRz = m2(Rz, NEG1);
        const ull qw2 = a2_(s2, B2);

        // acc += (q + b e) (x) R
        aw = f2(qw2, Rw, aw);
        aw = f2(ux2, nRx, aw);
        aw = f2(uy2, nRy, aw);
        aw = f2(uz2, nRz, aw);
        ax = f2(qw2, Rx, ax);
        ax = f2(ux2, Rw, ax);
        ax = f2(uy2, Rz, ax);
        ax = f2(uz2, nRy, ax);
        ay = f2(qw2, Ry, ay);
        ay = f2(ux2, nRz, ay);
        ay = f2(uy2, Rw, ay);
        ay = f2(uz2, Rx, ay);
        az = f2(qw2, Rz, az);
        az = f2(ux2, Ry, az);
        az = f2(uy2, nRx, az);
        az = f2(uz2, Rw, az);
    }

    // flat reduction over 16 ci warps (packed adds)
    if (ci > 0) {
        red[ci - 1][tx][0] = aw;
        red[ci - 1][tx][1] = ax;
        red[ci - 1][tx][2] = ay;
        red[ci - 1][tx][3] = az;
    }
    __syncthreads();
    if (ci == 0 && t < TOUT_) {
        #pragma unroll
        for (int k = 0; k < CIN_ - 1; ++k) {
            aw = a2_(aw, red[k][tx][0]);
            ax = a2_(ax, red[k][tx][1]);
            ay = a2_(ay, red[k][tx][2]);
            az = a2_(az, red[k][tx][3]);
        }
        float w0, w1, x0, x1, y0, y1, z0, z1;
        upk2(aw, w0, w1); upk2(ax, x0, x1); upk2(ay, y0, y1); upk2(az, z0, z1);
        float4* o4 = reinterpret_cast<float4*>(out) + (size_t)b * COUT_ * TOUT_ + t;
        o4[(size_t)(co0 + 0) * TOUT_] = make_float4(w0, x0, y0, z0);
        o4[(size_t)(co0 + 1) * TOUT_] = make_float4(w1, x1, y1, z1);
    }
}

extern "C" void kernel_launch(void* const* d_in, const int* in_sizes, int n_in,
                              void* d_out, int out_size)
{
    const float* x  = (const float*)d_in[0];
    const float* pa = (const float*)d_in[1];
    const float* pb = (const float*)d_in[2];
    const float* pc = (const float*)d_in[3];
    float* out = (float*)d_out;

    dim3 block(32, CIN_, 1);
    dim3 grid((TOUT_ + 31) / 32, COUT_ / NQ, B_);
    qconv1d_kernel<<<grid, block>>>(x, pa, pb, pc, out);
}